// round 1
// baseline (speedup 1.0000x reference)
#include <cuda_runtime.h>
#include <cuda_bf16.h>

#define BATCH 4
#define SQL   2048
#define SKL   2048
#define EDIM  1024
#define NH    16
#define HDIM  64

// Scratch for projected Q/K/V, layout [B*H][S][64]  (33.5 MB each)
__device__ float g_Q[(size_t)BATCH * NH * SQL * HDIM];
__device__ float g_K[(size_t)BATCH * NH * SKL * HDIM];
__device__ float g_V[(size_t)BATCH * NH * SKL * HDIM];

// ---------------------------------------------------------------------------
// Projection: Out[bh][s][d] = sum_e X[b][s][e] * W[h][e][d]
// grid (S/128, B*H), block 256.  Tile: 128(s) x 64(d=full head) x 16(e)
// ---------------------------------------------------------------------------
template <int WHICH>
__global__ __launch_bounds__(256) void proj_kernel(const float* __restrict__ X,
                                                   const float* __restrict__ W) {
    constexpr int BM = 128, BK = 16;
    __shared__ float Xst[BK][BM + 4];  // transposed [e][s]
    __shared__ float Ws[BK][HDIM];     // [e][d]

    float* Out = (WHICH == 0) ? g_Q : (WHICH == 1) ? g_K : g_V;

    const int bh = blockIdx.y;
    const int b  = bh >> 4;
    const int h  = bh & 15;
    const int s0 = blockIdx.x * BM;

    const float* Xb = X + (size_t)b * SQL * EDIM;
    const float* Wh = W + (size_t)h * EDIM * HDIM;
    float*       Ob = Out + ((size_t)bh * SQL + s0) * HDIM;

    const int tid = threadIdx.x;
    const int tx  = tid & 15;   // -> 4 output cols (d)
    const int ty  = tid >> 4;   // -> 8 output rows (s)

    float acc[8][4];
#pragma unroll
    for (int i = 0; i < 8; i++)
#pragma unroll
        for (int j = 0; j < 4; j++) acc[i][j] = 0.f;

    for (int e0 = 0; e0 < EDIM; e0 += BK) {
        // Load X tile 128x16, store transposed
#pragma unroll
        for (int t = 0; t < 2; t++) {
            int idx = tid + t * 256;            // 0..511
            int row = idx >> 2;                 // 0..127
            int e4  = (idx & 3) * 4;            // 0,4,8,12
            float4 v = *(const float4*)(Xb + (size_t)(s0 + row) * EDIM + e0 + e4);
            Xst[e4 + 0][row] = v.x;
            Xst[e4 + 1][row] = v.y;
            Xst[e4 + 2][row] = v.z;
            Xst[e4 + 3][row] = v.w;
        }
        // Load W tile 16x64
        {
            int kk = tid >> 4;                  // 0..15
            int c  = (tid & 15) * 4;            // 0..60
            *(float4*)&Ws[kk][c] = *(const float4*)(Wh + (size_t)(e0 + kk) * HDIM + c);
        }
        __syncthreads();

#pragma unroll
        for (int kk = 0; kk < BK; kk++) {
            float4 a0 = *(float4*)&Xst[kk][ty * 8];
            float4 a1 = *(float4*)&Xst[kk][ty * 8 + 4];
            float4 bv = *(float4*)&Ws[kk][tx * 4];
            float a[8] = {a0.x, a0.y, a0.z, a0.w, a1.x, a1.y, a1.z, a1.w};
            float bb[4] = {bv.x, bv.y, bv.z, bv.w};
#pragma unroll
            for (int i = 0; i < 8; i++)
#pragma unroll
                for (int j = 0; j < 4; j++) acc[i][j] = fmaf(a[i], bb[j], acc[i][j]);
        }
        __syncthreads();
    }

#pragma unroll
    for (int i = 0; i < 8; i++) {
        float4 o = make_float4(acc[i][0], acc[i][1], acc[i][2], acc[i][3]);
        *(float4*)(Ob + (size_t)(ty * 8 + i) * HDIM + tx * 4) = o;
    }
}

// ---------------------------------------------------------------------------
// Flash attention, fp32. grid (SQ/64, B*H), block 256 (16x16 threads, 4x4 regs)
// smem (dynamic): Qst[64][68] (d-major, pre-scaled), KP[64][68] (K^T, then P^T),
// Vs[64][68] (k-major)
// ---------------------------------------------------------------------------
#define ST 68

__global__ __launch_bounds__(256) void attn_kernel(float* __restrict__ out) {
    extern __shared__ float sm[];
    float* Qst = sm;
    float* KP  = sm + 64 * ST;
    float* Vs  = sm + 2 * 64 * ST;

    const int bh = blockIdx.y;
    const int b  = bh >> 4;
    const int h  = bh & 15;
    const int q0 = blockIdx.x * 64;

    const float* Qb = g_Q + ((size_t)bh * SQL + q0) * HDIM;
    const float* Kb = g_K + (size_t)bh * SKL * HDIM;
    const float* Vb = g_V + (size_t)bh * SKL * HDIM;

    const int tid = threadIdx.x;
    const int tx  = tid & 15;   // -> 4 cols (k for S, d for O)
    const int ty  = tid >> 4;   // -> 4 rows (q)
    const float scale = 0.125f; // 1/sqrt(64)

    // Load Q tile transposed + pre-scaled (once per block)
#pragma unroll
    for (int t = 0; t < 4; t++) {
        int idx = tid + t * 256;           // 0..1023
        int r   = idx >> 4;                // 0..63
        int d   = (idx & 15) * 4;          // 0..60
        float4 v = *(const float4*)(Qb + (size_t)r * HDIM + d);
        Qst[(d + 0) * ST + r] = v.x * scale;
        Qst[(d + 1) * ST + r] = v.y * scale;
        Qst[(d + 2) * ST + r] = v.z * scale;
        Qst[(d + 3) * ST + r] = v.w * scale;
    }

    float m[4], l[4], O[4][4];
#pragma unroll
    for (int i = 0; i < 4; i++) {
        m[i] = -1e30f;
        l[i] = 0.f;
#pragma unroll
        for (int j = 0; j < 4; j++) O[i][j] = 0.f;
    }

    for (int kt = 0; kt < SKL / 64; kt++) {
        __syncthreads();  // KP/Vs free to overwrite; also covers Qst on iter 0
        const float* Kt = Kb + (size_t)kt * 64 * HDIM;
        const float* Vt = Vb + (size_t)kt * 64 * HDIM;
#pragma unroll
        for (int t = 0; t < 4; t++) {
            int idx = tid + t * 256;
            int r   = idx >> 4;
            int d   = (idx & 15) * 4;
            float4 kv = *(const float4*)(Kt + (size_t)r * HDIM + d);
            KP[(d + 0) * ST + r] = kv.x;
            KP[(d + 1) * ST + r] = kv.y;
            KP[(d + 2) * ST + r] = kv.z;
            KP[(d + 3) * ST + r] = kv.w;
            float4 vv = *(const float4*)(Vt + (size_t)r * HDIM + d);
            *(float4*)&Vs[r * ST + d] = vv;
        }
        __syncthreads();

        // S = (Q*scale) @ K^T  (64x64x64), 4x4 per thread
        float s[4][4];
#pragma unroll
        for (int i = 0; i < 4; i++)
#pragma unroll
            for (int j = 0; j < 4; j++) s[i][j] = 0.f;

#pragma unroll 16
        for (int kk = 0; kk < 64; kk++) {
            float4 a  = *(float4*)&Qst[kk * ST + ty * 4];
            float4 bv = *(float4*)&KP[kk * ST + tx * 4];
            float av[4] = {a.x, a.y, a.z, a.w};
            float bb[4] = {bv.x, bv.y, bv.z, bv.w};
#pragma unroll
            for (int i = 0; i < 4; i++)
#pragma unroll
                for (int j = 0; j < 4; j++) s[i][j] = fmaf(av[i], bb[j], s[i][j]);
        }

        // Online softmax (row stats across the 16 tx lanes of each half-warp)
#pragma unroll
        for (int i = 0; i < 4; i++) {
            float mloc = fmaxf(fmaxf(s[i][0], s[i][1]), fmaxf(s[i][2], s[i][3]));
#pragma unroll
            for (int off = 8; off > 0; off >>= 1)
                mloc = fmaxf(mloc, __shfl_xor_sync(0xffffffffu, mloc, off));
            float mnew  = fmaxf(m[i], mloc);
            float alpha = __expf(m[i] - mnew);
            m[i] = mnew;
            float ls = 0.f;
#pragma unroll
            for (int j = 0; j < 4; j++) {
                s[i][j] = __expf(s[i][j] - mnew);
                ls += s[i][j];
            }
#pragma unroll
            for (int off = 8; off > 0; off >>= 1)
                ls += __shfl_xor_sync(0xffffffffu, ls, off);
            l[i] = l[i] * alpha + ls;
#pragma unroll
            for (int j = 0; j < 4; j++) O[i][j] *= alpha;
        }

        __syncthreads();  // everyone done reading K from KP
        // Store P transposed: KP[k][q]
#pragma unroll
        for (int j = 0; j < 4; j++) {
            float4 p = make_float4(s[0][j], s[1][j], s[2][j], s[3][j]);
            *(float4*)&KP[(tx * 4 + j) * ST + ty * 4] = p;
        }
        __syncthreads();

        // O += P @ V  (64x64x64)
#pragma unroll 16
        for (int kk = 0; kk < 64; kk++) {
            float4 a  = *(float4*)&KP[kk * ST + ty * 4];
            float4 bv = *(float4*)&Vs[kk * ST + tx * 4];
            float av[4] = {a.x, a.y, a.z, a.w};
            float bb[4] = {bv.x, bv.y, bv.z, bv.w};
#pragma unroll
            for (int i = 0; i < 4; i++)
#pragma unroll
                for (int j = 0; j < 4; j++) O[i][j] = fmaf(av[i], bb[j], O[i][j]);
        }
    }

    // Epilogue: out[b][q][d*H + h] = O / l   (reference's head-minor interleave)
#pragma unroll
    for (int i = 0; i < 4; i++) {
        float inv = 1.f / l[i];
        int q = q0 + ty * 4 + i;
#pragma unroll
        for (int j = 0; j < 4; j++) {
            int d = tx * 4 + j;
            out[(((size_t)b * SQL + q) * HDIM + d) * NH + h] = O[i][j] * inv;
        }
    }
}

// ---------------------------------------------------------------------------
extern "C" void kernel_launch(void* const* d_in, const int* in_sizes, int n_in,
                              void* d_out, int out_size) {
    const float* q  = (const float*)d_in[0];
    const float* k  = (const float*)d_in[1];
    const float* v  = (const float*)d_in[2];
    const float* Wq = (const float*)d_in[3];
    const float* Wk = (const float*)d_in[4];
    const float* Wv = (const float*)d_in[5];
    float* out = (float*)d_out;

    dim3 pgrid(SQL / 128, BATCH * NH);
    proj_kernel<0><<<pgrid, 256>>>(q, Wq);
    proj_kernel<1><<<pgrid, 256>>>(k, Wk);
    proj_kernel<2><<<pgrid, 256>>>(v, Wv);

    const int smem = 3 * 64 * ST * (int)sizeof(float);  // 52224 B
    cudaFuncSetAttribute(attn_kernel, cudaFuncAttributeMaxDynamicSharedMemorySize, smem);
    dim3 agrid(SQL / 64, BATCH * NH);
    attn_kernel<<<agrid, 256, smem>>>(out);
}

// round 3
// speedup vs baseline: 2.5122x; 2.5122x over previous
#include <cuda_runtime.h>
#include <cuda_bf16.h>

#define BATCH 4
#define SQL   2048
#define SKL   2048
#define EDIM  1024
#define NH    16
#define HDIM  64

// Scratch for projected Q/K/V (fp32), layout [B*H][S][64]
__device__ float g_Q[(size_t)BATCH * NH * SQL * HDIM];
__device__ float g_K[(size_t)BATCH * NH * SKL * HDIM];
__device__ float g_V[(size_t)BATCH * NH * SKL * HDIM];

// round-to-nearest fp32 -> tf32 (unbiased; truncation would bias dot products)
__device__ __forceinline__ unsigned f2tf(float f) {
    unsigned u;
    asm("cvt.rna.tf32.f32 %0, %1;" : "=r"(u) : "f"(f));
    return u;
}

__device__ __forceinline__ void mma_tf32(float* d, const unsigned* a, unsigned b0, unsigned b1) {
    asm volatile(
        "mma.sync.aligned.m16n8k8.row.col.f32.tf32.tf32.f32 "
        "{%0,%1,%2,%3}, {%4,%5,%6,%7}, {%8,%9}, {%0,%1,%2,%3};"
        : "+f"(d[0]), "+f"(d[1]), "+f"(d[2]), "+f"(d[3])
        : "r"(a[0]), "r"(a[1]), "r"(a[2]), "r"(a[3]), "r"(b0), "r"(b1));
}

// ---------------------------------------------------------------------------
// Projection: Out[bh][s][d] = sum_e X[b][s][e] * W[h][e][d]
// grid (SQL/128, B*H), block 256 (8 warps, 4x2 warp grid, warp tile 32x32)
// Tiles: BM=128(s) x BN=64(d) x BK=64(e). A=X row-major, B=W^T as [d][e].
// ---------------------------------------------------------------------------
#define PBK 64
#define PST 68   // smem row stride (floats) for 64-wide tiles

template <int WHICH>
__global__ __launch_bounds__(256) void proj_mma(const float* __restrict__ X,
                                                const float* __restrict__ W) {
    extern __shared__ unsigned psm[];
    unsigned* Xs = psm;                 // [128][PST]  tf32, [s][e]
    unsigned* Wt = psm + 128 * PST;     // [64][PST]   tf32, [d][e]

    float* Out = (WHICH == 0) ? g_Q : (WHICH == 1) ? g_K : g_V;

    const int bh = blockIdx.y;
    const int b  = bh >> 4;
    const int h  = bh & 15;
    const int s0 = blockIdx.x * 128;

    const float* Xb = X + ((size_t)b * SQL + s0) * EDIM;
    const float* Wh = W + (size_t)h * EDIM * HDIM;
    float*       Ob = Out + ((size_t)bh * SQL + s0) * HDIM;

    const int tid  = threadIdx.x;
    const int warp = tid >> 5;
    const int lane = tid & 31;
    const int g    = lane >> 2;   // groupID
    const int t    = lane & 3;    // thread-in-group
    const int wm   = warp >> 1;   // 0..3 -> 32 rows each
    const int wn   = warp & 1;    // 0..1 -> 32 cols each

    float acc[2][4][4];
#pragma unroll
    for (int mt = 0; mt < 2; mt++)
#pragma unroll
        for (int nt = 0; nt < 4; nt++)
#pragma unroll
            for (int r = 0; r < 4; r++) acc[mt][nt][r] = 0.f;

    for (int e0 = 0; e0 < EDIM; e0 += PBK) {
        // X tile 128x64 -> Xs (tf32), float4 loads
#pragma unroll
        for (int it = 0; it < 8; it++) {
            int idx = tid + it * 256;          // 0..2047 float4
            int r   = idx >> 4;                // 0..127
            int c   = idx & 15;                // 0..15
            float4 v = *(const float4*)(Xb + (size_t)r * EDIM + e0 + c * 4);
            uint4 u = make_uint4(f2tf(v.x), f2tf(v.y), f2tf(v.z), f2tf(v.w));
            *(uint4*)&Xs[r * PST + c * 4] = u;
        }
        // W tile 64x64 transposed -> Wt[d][e], scalar (coalesced LDG along d)
#pragma unroll
        for (int it = 0; it < 16; it++) {
            int idx = tid + it * 256;          // 0..4095
            int d   = idx & 63;
            int e   = idx >> 6;                // 0..63
            Wt[d * PST + e] = f2tf(Wh[(size_t)(e0 + e) * HDIM + d]);
        }
        __syncthreads();

#pragma unroll
        for (int ks = 0; ks < 8; ks++) {
            int k0 = ks * 8;
            unsigned a[2][4];
#pragma unroll
            for (int mt = 0; mt < 2; mt++) {
                int row = wm * 32 + mt * 16;
                a[mt][0] = Xs[(row + g) * PST + k0 + t];
                a[mt][1] = Xs[(row + 8 + g) * PST + k0 + t];
                a[mt][2] = Xs[(row + g) * PST + k0 + t + 4];
                a[mt][3] = Xs[(row + 8 + g) * PST + k0 + t + 4];
            }
#pragma unroll
            for (int nt = 0; nt < 4; nt++) {
                int col = wn * 32 + nt * 8;
                unsigned b0 = Wt[(col + g) * PST + k0 + t];
                unsigned b1 = Wt[(col + g) * PST + k0 + t + 4];
#pragma unroll
                for (int mt = 0; mt < 2; mt++) mma_tf32(acc[mt][nt], a[mt], b0, b1);
            }
        }
        __syncthreads();
    }

#pragma unroll
    for (int mt = 0; mt < 2; mt++) {
        int row = wm * 32 + mt * 16;
#pragma unroll
        for (int nt = 0; nt < 4; nt++) {
            int col = wn * 32 + nt * 8 + 2 * t;
            *(float2*)&Ob[(size_t)(row + g) * HDIM + col] =
                make_float2(acc[mt][nt][0], acc[mt][nt][1]);
            *(float2*)&Ob[(size_t)(row + 8 + g) * HDIM + col] =
                make_float2(acc[mt][nt][2], acc[mt][nt][3]);
        }
    }
}

// ---------------------------------------------------------------------------
// Flash attention, tf32 mma. grid (SQL/128, B*H), block 256 (8 warps).
// Each warp owns 16 q-rows x full 64 kv x full 64 d (softmax warp-local).
// smem: QPs[128][68] (Q tf32 frags preloaded to regs, then reused for P),
//       Ks[64][68] ([k][d]), Vt[64][68] ([d][k], transposed).
// ---------------------------------------------------------------------------
#define AST 68

__global__ __launch_bounds__(256) void attn_mma(float* __restrict__ out) {
    extern __shared__ unsigned asm_[];
    unsigned* QPs = asm_;                  // [128][AST]
    unsigned* Ks  = asm_ + 128 * AST;      // [64][AST]
    unsigned* Vt  = Ks + 64 * AST;         // [64][AST]

    const int bh = blockIdx.y;
    const int b  = bh >> 4;
    const int h  = bh & 15;
    const int q0 = blockIdx.x * 128;

    const float* Qb = g_Q + ((size_t)bh * SQL + q0) * HDIM;
    const float* Kb = g_K + (size_t)bh * SKL * HDIM;
    const float* Vb = g_V + (size_t)bh * SKL * HDIM;

    const int tid  = threadIdx.x;
    const int warp = tid >> 5;
    const int lane = tid & 31;
    const int g    = lane >> 2;
    const int t    = lane & 3;
    const int m0   = warp * 16;

    // Load Q tile (pre-scaled by 1/sqrt(64)) into smem as tf32
#pragma unroll
    for (int it = 0; it < 8; it++) {
        int idx = tid + it * 256;          // 0..2047 float4
        int r   = idx >> 4;
        int c   = idx & 15;
        float4 v = *(const float4*)(Qb + (size_t)r * HDIM + c * 4);
        uint4 u = make_uint4(f2tf(v.x * 0.125f), f2tf(v.y * 0.125f),
                             f2tf(v.z * 0.125f), f2tf(v.w * 0.125f));
        *(uint4*)&QPs[r * AST + c * 4] = u;
    }
    __syncthreads();

    // Preload Q fragments for all 8 k-steps (Q smem becomes P buffer after)
    unsigned qf[8][4];
#pragma unroll
    for (int ks = 0; ks < 8; ks++) {
        int k0 = ks * 8;
        qf[ks][0] = QPs[(m0 + g) * AST + k0 + t];
        qf[ks][1] = QPs[(m0 + 8 + g) * AST + k0 + t];
        qf[ks][2] = QPs[(m0 + g) * AST + k0 + t + 4];
        qf[ks][3] = QPs[(m0 + 8 + g) * AST + k0 + t + 4];
    }

    float Of[8][4];
#pragma unroll
    for (int nt = 0; nt < 8; nt++)
#pragma unroll
        for (int r = 0; r < 4; r++) Of[nt][r] = 0.f;
    float mr0 = -1e30f, mr1 = -1e30f, lr0 = 0.f, lr1 = 0.f;

    for (int kt = 0; kt < SKL / 64; kt++) {
        __syncthreads();  // prev iter's PV reads (QPs/Vt) + Q-frag preload done

        const float* Kt = Kb + (size_t)kt * 64 * HDIM;
        const float* Vp = Vb + (size_t)kt * 64 * HDIM;
        // K tile [k][d] -> Ks, float4
#pragma unroll
        for (int it = 0; it < 4; it++) {
            int idx = tid + it * 256;      // 0..1023 float4
            int r   = idx >> 4;
            int c   = idx & 15;
            float4 v = *(const float4*)(Kt + (size_t)r * HDIM + c * 4);
            uint4 u = make_uint4(f2tf(v.x), f2tf(v.y), f2tf(v.z), f2tf(v.w));
            *(uint4*)&Ks[r * AST + c * 4] = u;
        }
        // V tile transposed -> Vt[d][k], coalesced LDG along d
#pragma unroll
        for (int it = 0; it < 16; it++) {
            int idx = tid + it * 256;      // 0..4095
            int d   = idx & 63;
            int r   = idx >> 6;
            Vt[d * AST + r] = f2tf(Vp[(size_t)r * HDIM + d]);
        }
        __syncthreads();

        // S = (Q*scale) @ K^T
        float sf[8][4];
#pragma unroll
        for (int nt = 0; nt < 8; nt++)
#pragma unroll
            for (int r = 0; r < 4; r++) sf[nt][r] = 0.f;
#pragma unroll
        for (int ks = 0; ks < 8; ks++) {
            int k0 = ks * 8;
#pragma unroll
            for (int nt = 0; nt < 8; nt++) {
                unsigned b0 = Ks[(nt * 8 + g) * AST + k0 + t];
                unsigned b1 = Ks[(nt * 8 + g) * AST + k0 + t + 4];
                mma_tf32(sf[nt], qf[ks], b0, b1);
            }
        }

        // Online softmax. Row r0 = m0+g (regs 0,1), row r1 = m0+8+g (regs 2,3).
        float mx0 = -1e30f, mx1 = -1e30f;
#pragma unroll
        for (int nt = 0; nt < 8; nt++) {
            mx0 = fmaxf(mx0, fmaxf(sf[nt][0], sf[nt][1]));
            mx1 = fmaxf(mx1, fmaxf(sf[nt][2], sf[nt][3]));
        }
        mx0 = fmaxf(mx0, __shfl_xor_sync(0xffffffffu, mx0, 1));
        mx0 = fmaxf(mx0, __shfl_xor_sync(0xffffffffu, mx0, 2));
        mx1 = fmaxf(mx1, __shfl_xor_sync(0xffffffffu, mx1, 1));
        mx1 = fmaxf(mx1, __shfl_xor_sync(0xffffffffu, mx1, 2));
        float mn0 = fmaxf(mr0, mx0), mn1 = fmaxf(mr1, mx1);
        float al0 = __expf(mr0 - mn0), al1 = __expf(mr1 - mn1);
        mr0 = mn0; mr1 = mn1;
        float sum0 = 0.f, sum1 = 0.f;
#pragma unroll
        for (int nt = 0; nt < 8; nt++) {
            sf[nt][0] = __expf(sf[nt][0] - mn0); sum0 += sf[nt][0];
            sf[nt][1] = __expf(sf[nt][1] - mn0); sum0 += sf[nt][1];
            sf[nt][2] = __expf(sf[nt][2] - mn1); sum1 += sf[nt][2];
            sf[nt][3] = __expf(sf[nt][3] - mn1); sum1 += sf[nt][3];
        }
        sum0 += __shfl_xor_sync(0xffffffffu, sum0, 1);
        sum0 += __shfl_xor_sync(0xffffffffu, sum0, 2);
        sum1 += __shfl_xor_sync(0xffffffffu, sum1, 1);
        sum1 += __shfl_xor_sync(0xffffffffu, sum1, 2);
        lr0 = lr0 * al0 + sum0;
        lr1 = lr1 * al1 + sum1;
#pragma unroll
        for (int nt = 0; nt < 8; nt++) {
            Of[nt][0] *= al0; Of[nt][1] *= al0;
            Of[nt][2] *= al1; Of[nt][3] *= al1;
        }

        // Write P (tf32) into QPs. Safe: Q frags are in regs, peers only read Ks.
#pragma unroll
        for (int nt = 0; nt < 8; nt++) {
            int col = nt * 8 + 2 * t;
            *(uint2*)&QPs[(m0 + g) * AST + col] =
                make_uint2(f2tf(sf[nt][0]), f2tf(sf[nt][1]));
            *(uint2*)&QPs[(m0 + 8 + g) * AST + col] =
                make_uint2(f2tf(sf[nt][2]), f2tf(sf[nt][3]));
        }
        __syncthreads();

        // O += P @ V   (A = P[q][kv], B = Vt[d][kv])
#pragma unroll
        for (int ks = 0; ks < 8; ks++) {
            int k0 = ks * 8;
            unsigned pa[4];
            pa[0] = QPs[(m0 + g) * AST + k0 + t];
            pa[1] = QPs[(m0 + 8 + g) * AST + k0 + t];
            pa[2] = QPs[(m0 + g) * AST + k0 + t + 4];
            pa[3] = QPs[(m0 + 8 + g) * AST + k0 + t + 4];
#pragma unroll
            for (int nt = 0; nt < 8; nt++) {
                unsigned b0 = Vt[(nt * 8 + g) * AST + k0 + t];
                unsigned b1 = Vt[(nt * 8 + g) * AST + k0 + t + 4];
                mma_tf32(Of[nt], pa, b0, b1);
            }
        }
    }

    // Epilogue: out[b][q][d*NH + h] = O / l
    float inv0 = 1.f / lr0, inv1 = 1.f / lr1;
    int q_0 = q0 + m0 + g;
    int q_1 = q_0 + 8;
#pragma unroll
    for (int nt = 0; nt < 8; nt++) {
        int d0 = nt * 8 + 2 * t;
        size_t base0 = (((size_t)b * SQL + q_0) * HDIM + d0) * NH + h;
        size_t base1 = (((size_t)b * SQL + q_1) * HDIM + d0) * NH + h;
        out[base0]      = Of[nt][0] * inv0;
        out[base0 + NH] = Of[nt][1] * inv0;
        out[base1]      = Of[nt][2] * inv1;
        out[base1 + NH] = Of[nt][3] * inv1;
    }
}

// ---------------------------------------------------------------------------
extern "C" void kernel_launch(void* const* d_in, const int* in_sizes, int n_in,
                              void* d_out, int out_size) {
    const float* q  = (const float*)d_in[0];
    const float* k  = (const float*)d_in[1];
    const float* v  = (const float*)d_in[2];
    const float* Wq = (const float*)d_in[3];
    const float* Wk = (const float*)d_in[4];
    const float* Wv = (const float*)d_in[5];
    float* out = (float*)d_out;

    const int psmem = (128 + 64) * PST * (int)sizeof(unsigned);  // 52224 B
    cudaFuncSetAttribute(proj_mma<0>, cudaFuncAttributeMaxDynamicSharedMemorySize, psmem);
    cudaFuncSetAttribute(proj_mma<1>, cudaFuncAttributeMaxDynamicSharedMemorySize, psmem);
    cudaFuncSetAttribute(proj_mma<2>, cudaFuncAttributeMaxDynamicSharedMemorySize, psmem);
    dim3 pgrid(SQL / 128, BATCH * NH);
    proj_mma<0><<<pgrid, 256, psmem>>>(q, Wq);
    proj_mma<1><<<pgrid, 256, psmem>>>(k, Wk);
    proj_mma<2><<<pgrid, 256, psmem>>>(v, Wv);

    const int asmem = (128 + 64 + 64) * AST * (int)sizeof(unsigned);  // 69632 B
    cudaFuncSetAttribute(attn_mma, cudaFuncAttributeMaxDynamicSharedMemorySize, asmem);
    dim3 agrid(SQL / 128, BATCH * NH);
    attn_mma<<<agrid, 256, asmem>>>(out);
}